// round 7
// baseline (speedup 1.0000x reference)
#include <cuda_runtime.h>
#include <cuda_bf16.h>
#include <cstdint>
#include <cstring>

// ---------------------------------------------------------------------------
// GAT layer: out = concat( softmax(mask(lrelu(s_i + t_j))) @ h , h )
//   X:[1024,75,512] fp32  A:[75,75] int32  W:[512,256] fp32  a:[2,256,1] fp32
//   out:[1024,75,512] fp32
// NOTE: toolchain targets sm_100 (no 'a' features) -> tcgen05 unavailable.
// Phase 0: W split into bf16 hi/lo scratch ([k][n], tiny prepass)
// Phase 1: h = X @ W, mma.sync bf16 3-term split, BM=128 BN=256 BK=32
// Phase 2: attention + aggregation, 2 CTAs per batch
// ---------------------------------------------------------------------------

#define BATCH 1024
#define NNODE 75
#define FIN   512
#define FOUT  256
#define MROWS (BATCH * NNODE)   // 76800

// ===================== Phase 0: W hi/lo split prepass ======================
__device__ __nv_bfloat16 g_W_hi[FIN * FOUT];   // [k][n], same layout as W
__device__ __nv_bfloat16 g_W_lo[FIN * FOUT];

__global__ void w_split_kernel(const float* __restrict__ W) {
    const int idx = blockIdx.x * 256 + threadIdx.x;
    if (idx < FIN * FOUT) {
        const float v = W[idx];
        const __nv_bfloat16 h = __float2bfloat16(v);
        g_W_hi[idx] = h;
        g_W_lo[idx] = __float2bfloat16(v - __bfloat162float(h));
    }
}

// ===================== mma.sync helpers ====================================
__device__ __forceinline__ unsigned pack_bf16x2(float a, float b) {
    __nv_bfloat162 t = __floats2bfloat162_rn(a, b);
    unsigned u; memcpy(&u, &t, 4); return u;
}
__device__ __forceinline__ void ldsm_x4(unsigned r[4], unsigned addr) {
    asm volatile("ldmatrix.sync.aligned.m8n8.x4.shared.b16 {%0,%1,%2,%3}, [%4];"
                 : "=r"(r[0]), "=r"(r[1]), "=r"(r[2]), "=r"(r[3]) : "r"(addr));
}
__device__ __forceinline__ void ldsm_x2_t(unsigned r[2], unsigned addr) {
    asm volatile("ldmatrix.sync.aligned.m8n8.x2.trans.shared.b16 {%0,%1}, [%2];"
                 : "=r"(r[0]), "=r"(r[1]) : "r"(addr));
}
__device__ __forceinline__ void mma_bf16(float d[4], const unsigned a[4], const unsigned b[2]) {
    asm volatile(
        "mma.sync.aligned.m16n8k16.row.col.f32.bf16.bf16.f32 "
        "{%0,%1,%2,%3},{%4,%5,%6,%7},{%8,%9},{%0,%1,%2,%3};"
        : "+f"(d[0]), "+f"(d[1]), "+f"(d[2]), "+f"(d[3])
        : "r"(a[0]), "r"(a[1]), "r"(a[2]), "r"(a[3]), "r"(b[0]), "r"(b[1]));
}
__device__ __forceinline__ void cp_async16(unsigned dst, const void* src) {
    asm volatile("cp.async.cg.shared.global [%0], [%1], 16;" :: "r"(dst), "l"(src));
}
#define CP_COMMIT() asm volatile("cp.async.commit_group;" ::: "memory")
#define CP_WAIT0()  asm volatile("cp.async.wait_group 0;" ::: "memory")

// ===================== Phase 1: GEMM =======================================
// M=76800 K=512 N=256. CTA tile 128x256, BK=32, 256 thr (8 warps, 2x4 grid,
// warp tile 64x64). 3-term split: Ahi*Bhi + Ahi*Blo + Alo*Bhi.
#define G_BM 128
#define G_BN 256
#define G_BK 32
#define NKT  (FIN / G_BK)   // 16
#define SA 40     // A smem row stride (bf16): 80B, conflict-free (proven R4)
#define SB 264    // B smem row stride: 528B -> same 4-word/row bank shift as R4
#define A_HI_OFF 0
#define A_LO_OFF (G_BM * SA)                        // 5120
#define B_HI_OFF (2 * G_BM * SA)                    // 10240
#define B_LO_OFF (2 * G_BM * SA + G_BK * SB)        // 18688
#define STAGE_ELEMS (2 * G_BM * SA + 2 * G_BK * SB) // 27136
#define GEMM_SMEM_BYTES (2 * STAGE_ELEMS * 2)       // 108544

__global__ __launch_bounds__(256, 1)
void gat_gemm_kernel(const float* __restrict__ X, float* __restrict__ out)
{
    extern __shared__ __nv_bfloat16 sm[];
    const unsigned smem_u32 = (unsigned)__cvta_generic_to_shared(sm);

    const int tid  = threadIdx.x;
    const int lane = tid & 31;
    const int wid  = tid >> 5;
    const int warp_m = wid & 1;   // 2 warps along M (64 rows)
    const int warp_n = wid >> 1;  // 4 warps along N (64 cols)

    const float* Ap = X + (size_t)blockIdx.x * G_BM * FIN;

    float c[4][8][4];
    #pragma unroll
    for (int mt = 0; mt < 4; mt++)
        #pragma unroll
        for (int nt = 0; nt < 8; nt++)
            #pragma unroll
            for (int i = 0; i < 4; i++) c[mt][nt][i] = 0.0f;

    float4 aR[4];

    // A loader: 128x32 fp32 = 1024 float4; idx -> row=idx>>3, c4=idx&7
    auto loadA = [&](int t) {
        #pragma unroll
        for (int l = 0; l < 4; l++) {
            const int ia = tid + l * 256;
            aR[l] = *reinterpret_cast<const float4*>(
                Ap + (size_t)(ia >> 3) * FIN + t * G_BK + (ia & 7) * 4);
        }
    };
    auto storeA = [&](int s) {
        const int base = s * STAGE_ELEMS;
        #pragma unroll
        for (int l = 0; l < 4; l++) {
            const int ia = tid + l * 256;
            const int off = (ia >> 3) * SA + (ia & 7) * 4;
            const float4 v = aR[l];
            const float h0 = __bfloat162float(__float2bfloat16(v.x));
            const float h1 = __bfloat162float(__float2bfloat16(v.y));
            const float h2 = __bfloat162float(__float2bfloat16(v.z));
            const float h3 = __bfloat162float(__float2bfloat16(v.w));
            *reinterpret_cast<uint2*>(&sm[base + A_HI_OFF + off]) =
                make_uint2(pack_bf16x2(v.x, v.y), pack_bf16x2(v.z, v.w));
            *reinterpret_cast<uint2*>(&sm[base + A_LO_OFF + off]) =
                make_uint2(pack_bf16x2(v.x - h0, v.y - h1), pack_bf16x2(v.z - h2, v.w - h3));
        }
    };
    // B loader: cp.async 16B chunks from pre-split scratch. 32 rows x 32 chunks.
    auto loadB_async = [&](int s, int t) {
        const int base = s * STAGE_ELEMS;
        #pragma unroll
        for (int l = 0; l < 4; l++) {
            const int ib = tid + l * 256;
            const int row = ib >> 5, c16 = ib & 31;
            const int soff = row * SB + c16 * 8;               // elems
            const int goff = (t * G_BK + row) * FOUT + c16 * 8;
            cp_async16(smem_u32 + 2u * (base + B_HI_OFF + soff), &g_W_hi[goff]);
            cp_async16(smem_u32 + 2u * (base + B_LO_OFF + soff), &g_W_lo[goff]);
        }
    };

    // prologue: stage 0
    loadB_async(0, 0); CP_COMMIT();
    loadA(0);
    storeA(0);
    CP_WAIT0();
    __syncthreads();

    #pragma unroll 1
    for (int t = 0; t < NKT; t++) {
        const int s = t & 1;
        if (t + 1 < NKT) {
            loadB_async(s ^ 1, t + 1); CP_COMMIT();
            loadA(t + 1);
        }

        const int sbase = s * STAGE_ELEMS;
        #pragma unroll
        for (int ks = 0; ks < 2; ks++) {
            unsigned bhi[8][2], blo[8][2];
            const int brow = ks * 16 + (lane & 15);
            #pragma unroll
            for (int nt = 0; nt < 8; nt++) {
                const int bcol = warp_n * 64 + nt * 8;
                ldsm_x2_t(bhi[nt], smem_u32 + 2u * (sbase + B_HI_OFF + brow * SB + bcol));
                ldsm_x2_t(blo[nt], smem_u32 + 2u * (sbase + B_LO_OFF + brow * SB + bcol));
            }
            const int arow = warp_m * 64 + (lane & 15);
            const int acol = ks * 16 + (lane >> 4) * 8;
            #pragma unroll
            for (int mt = 0; mt < 4; mt++) {
                unsigned ahi[4], alo[4];
                const int aoff = (arow + mt * 16) * SA + acol;
                ldsm_x4(ahi, smem_u32 + 2u * (sbase + A_HI_OFF + aoff));
                ldsm_x4(alo, smem_u32 + 2u * (sbase + A_LO_OFF + aoff));
                #pragma unroll
                for (int nt = 0; nt < 8; nt++) {
                    mma_bf16(c[mt][nt], ahi, bhi[nt]);
                    mma_bf16(c[mt][nt], ahi, blo[nt]);
                    mma_bf16(c[mt][nt], alo, bhi[nt]);
                }
            }
        }

        if (t + 1 < NKT) {
            storeA(s ^ 1);
            CP_WAIT0();
            __syncthreads();
        }
    }

    // epilogue: write h into out[..., 256:512]
    const int row0 = blockIdx.x * G_BM + warp_m * 64 + (lane >> 2);
    const int col0 = warp_n * 64 + (lane & 3) * 2;
    #pragma unroll
    for (int mt = 0; mt < 4; mt++) {
        #pragma unroll
        for (int nt = 0; nt < 8; nt++) {
            float* p0 = out + (size_t)(row0 + mt * 16) * 512 + 256 + col0 + nt * 8;
            float* p1 = out + (size_t)(row0 + mt * 16 + 8) * 512 + 256 + col0 + nt * 8;
            *reinterpret_cast<float2*>(p0) = make_float2(c[mt][nt][0], c[mt][nt][1]);
            *reinterpret_cast<float2*>(p1) = make_float2(c[mt][nt][2], c[mt][nt][3]);
        }
    }
}

// ===================== Phase 2: attention + aggregation ====================
// 2 CTAs per batch (grid (1024,2)), each owns 128 output cols. 256 threads.
// smem floats: hs[75*128] half-h, mb[80*76] softmax rows (pad rows zero),
// sv/tv[80]. s/t dot-products stream full h rows from gmem (L2-hot).
#define MB_STRIDE 76
#define SM_HS   0
#define SM_MB   (SM_HS + NNODE * 128)             // 9600
#define SM_SV   (SM_MB + 80 * MB_STRIDE)          // 15680
#define SM_TV   (SM_SV + 80)                      // 15760
#define ATTN_SMEM_BYTES ((SM_TV + 80) * 4)        // 63360

__global__ __launch_bounds__(256, 3)
void gat_attn_kernel(const int* __restrict__ A,
                     const float* __restrict__ avec,  // [2*256]
                     float* __restrict__ out)
{
    extern __shared__ float smf[];
    float* hs = smf + SM_HS;
    float* mb = smf + SM_MB;
    float* sv = smf + SM_SV;
    float* tv = smf + SM_TV;

    const int b    = blockIdx.x;
    const int colbase = blockIdx.y * 128;
    const int tid  = threadIdx.x;
    const int warp = tid >> 5;
    const int lane = tid & 31;

    float* outb = out + (size_t)b * NNODE * 512;
    const float* hsrc = outb + 256;

    // Load this CTA's 128-col half of h[b] into smem.
    for (int idx = tid; idx < NNODE * 32; idx += 256) {
        const int i  = idx >> 5;
        const int f4 = idx & 31;
        *reinterpret_cast<float4*>(&hs[i * 128 + f4 * 4]) =
            *reinterpret_cast<const float4*>(hsrc + (size_t)i * 512 + colbase + f4 * 4);
    }
    // Mask bias (padded stride); zero pad rows 75..79.
    for (int idx = tid; idx < NNODE * NNODE; idx += 256)
        mb[(idx / NNODE) * MB_STRIDE + (idx % NNODE)] = A[idx] ? 0.0f : -1.0e9f;
    for (int idx = tid; idx < 5 * MB_STRIDE; idx += 256)
        mb[75 * MB_STRIDE + idx] = 0.0f;
    __syncthreads();

    // s_i = h_i . a0 ; t_i = h_i . a1  (warp per row, full h rows from L2)
    for (int i = warp; i < NNODE; i += 8) {
        float s0 = 0.0f, s1 = 0.0f;
        #pragma unroll
        for (int r = 0; r < 8; r++) {
            const int f = lane + r * 32;
            const float hv = hsrc[(size_t)i * 512 + f];
            s0 = fmaf(hv, avec[f], s0);
            s1 = fmaf(hv, avec[256 + f], s1);
        }
        #pragma unroll
        for (int o = 16; o; o >>= 1) {
            s0 += __shfl_xor_sync(0xffffffffu, s0, o);
            s1 += __shfl_xor_sync(0xffffffffu, s1, o);
        }
        if (lane == 0) { sv[i] = s0; tv[i] = s1; }
    }
    __syncthreads();

    // Softmax of all 75 rows in place over mb.
    for (int i = warp; i < NNODE; i += 8) {
        const float si = sv[i];
        float ev[3];
        float m = -3.0e38f;
        #pragma unroll
        for (int r = 0; r < 3; r++) {
            const int j = lane + r * 32;
            float e;
            if (j < NNODE) {
                e = si + tv[j];
                e = (e > 0.0f) ? e : 0.2f * e;     // leaky relu
                e += mb[i * MB_STRIDE + j];
            } else {
                e = -3.0e38f;
            }
            ev[r] = e;
            m = fmaxf(m, e);
        }
        #pragma unroll
        for (int o = 16; o; o >>= 1)
            m = fmaxf(m, __shfl_xor_sync(0xffffffffu, m, o));
        float sum = 0.0f;
        #pragma unroll
        for (int r = 0; r < 3; r++) {
            const int j = lane + r * 32;
            const float p = (j < NNODE) ? __expf(ev[r] - m) : 0.0f;
            ev[r] = p;
            sum += p;
        }
        #pragma unroll
        for (int o = 16; o; o >>= 1)
            sum += __shfl_xor_sync(0xffffffffu, sum, o);
        const float inv = 1.0f / sum;
        #pragma unroll
        for (int r = 0; r < 3; r++) {
            const int j = lane + r * 32;
            if (j < NNODE) mb[i * MB_STRIDE + j] = ev[r] * inv;
        }
    }
    __syncthreads();

    // Aggregation: thread owns 4 cols (colbase + (tid&31)*4) and rows
    // {g, g+8, ..., g+72}, g = warp id (uniform -> broadcast alpha loads).
    const int g  = warp;
    const int cc = tid & 31;
    const float4* hs4 = reinterpret_cast<const float4*>(hs);

    float4 acc[10];
    #pragma unroll
    for (int r = 0; r < 10; r++) acc[r] = make_float4(0.f, 0.f, 0.f, 0.f);

    #pragma unroll 1
    for (int j = 0; j < NNODE; j++) {
        const float4 hv = hs4[j * 32 + cc];
        const float* ap = &mb[g * MB_STRIDE + j];
        #pragma unroll
        for (int r = 0; r < 10; r++) {
            const float a = ap[r * 8 * MB_STRIDE];   // row g+8r (pad rows = 0)
            acc[r].x = fmaf(a, hv.x, acc[r].x);
            acc[r].y = fmaf(a, hv.y, acc[r].y);
            acc[r].z = fmaf(a, hv.z, acc[r].z);
            acc[r].w = fmaf(a, hv.w, acc[r].w);
        }
    }
    #pragma unroll
    for (int r = 0; r < 10; r++) {
        const int row = g + 8 * r;
        if (row < NNODE)
            *reinterpret_cast<float4*>(outb + (size_t)row * 512 + colbase + cc * 4) = acc[r];
    }
}

// ===========================================================================

extern "C" void kernel_launch(void* const* d_in, const int* in_sizes, int n_in,
                              void* d_out, int out_size)
{
    const float* X = (const float*)d_in[0];
    const int*   A = (const int*)d_in[1];
    const float* W = (const float*)d_in[2];
    const float* a = (const float*)d_in[3];
    float* out = (float*)d_out;

    cudaFuncSetAttribute(gat_gemm_kernel,
                         cudaFuncAttributeMaxDynamicSharedMemorySize, GEMM_SMEM_BYTES);
    cudaFuncSetAttribute(gat_attn_kernel,
                         cudaFuncAttributeMaxDynamicSharedMemorySize, ATTN_SMEM_BYTES);

    w_split_kernel<<<(FIN * FOUT + 255) / 256, 256>>>(W);
    gat_gemm_kernel<<<MROWS / G_BM, 256, GEMM_SMEM_BYTES>>>(X, out);
    gat_attn_kernel<<<dim3(BATCH, 2), 256, ATTN_SMEM_BYTES>>>(A, a, out);
}

// round 8
// speedup vs baseline: 1.0113x; 1.0113x over previous
#include <cuda_runtime.h>
#include <cuda_bf16.h>
#include <cstdint>
#include <cstring>

// ---------------------------------------------------------------------------
// GAT layer: out = concat( softmax(mask(lrelu(s_i + t_j))) @ h , h )
//   X:[1024,75,512] fp32  A:[75,75] int32  W:[512,256] fp32  a:[2,256,1] fp32
//   out:[1024,75,512] fp32
// Toolchain targets sm_100 (no 'a') -> tcgen05 unavailable; mma.sync path.
// Phase 0: W split into bf16 hi/lo scratch ([k][n])
// Phase 1: h = X @ W, mma.sync bf16 3-term split, cp.async 3-stage pipeline
// Phase 2: attention + aggregation (R4 kernel, measured 132.6us)
// ---------------------------------------------------------------------------

#define BATCH 1024
#define NNODE 75
#define FIN   512
#define FOUT  256
#define MROWS (BATCH * NNODE)   // 76800

// ===================== Phase 0: W hi/lo split prepass ======================
__device__ __nv_bfloat16 g_W_hi[FIN * FOUT];   // [k][n]
__device__ __nv_bfloat16 g_W_lo[FIN * FOUT];

__global__ void w_split_kernel(const float* __restrict__ W) {
    const int idx = blockIdx.x * 256 + threadIdx.x;
    if (idx < FIN * FOUT) {
        const float v = W[idx];
        const __nv_bfloat16 h = __float2bfloat16(v);
        g_W_hi[idx] = h;
        g_W_lo[idx] = __float2bfloat16(v - __bfloat162float(h));
    }
}

// ===================== helpers =============================================
__device__ __forceinline__ unsigned pack_bf16x2(float a, float b) {
    __nv_bfloat162 t = __floats2bfloat162_rn(a, b);
    unsigned u; memcpy(&u, &t, 4); return u;
}
__device__ __forceinline__ void ldsm_x4(unsigned r[4], unsigned addr) {
    asm volatile("ldmatrix.sync.aligned.m8n8.x4.shared.b16 {%0,%1,%2,%3}, [%4];"
                 : "=r"(r[0]), "=r"(r[1]), "=r"(r[2]), "=r"(r[3]) : "r"(addr));
}
__device__ __forceinline__ void ldsm_x2_t(unsigned r[2], unsigned addr) {
    asm volatile("ldmatrix.sync.aligned.m8n8.x2.trans.shared.b16 {%0,%1}, [%2];"
                 : "=r"(r[0]), "=r"(r[1]) : "r"(addr));
}
__device__ __forceinline__ void mma_bf16(float d[4], const unsigned a[4], const unsigned b[2]) {
    asm volatile(
        "mma.sync.aligned.m16n8k16.row.col.f32.bf16.bf16.f32 "
        "{%0,%1,%2,%3},{%4,%5,%6,%7},{%8,%9},{%0,%1,%2,%3};"
        : "+f"(d[0]), "+f"(d[1]), "+f"(d[2]), "+f"(d[3])
        : "r"(a[0]), "r"(a[1]), "r"(a[2]), "r"(a[3]), "r"(b[0]), "r"(b[1]));
}
__device__ __forceinline__ void cp_async16(unsigned dst, const void* src) {
    asm volatile("cp.async.cg.shared.global [%0], [%1], 16;" :: "r"(dst), "l"(src));
}
#define CP_COMMIT() asm volatile("cp.async.commit_group;" ::: "memory")
template<int N> __device__ __forceinline__ void cp_wait() {
    asm volatile("cp.async.wait_group %0;" :: "n"(N) : "memory");
}

// ===================== Phase 1: GEMM =======================================
// M=76800 K=512 N=256. CTA 128x256, BK=32, 256 thr, warp tile 64x64 (2x4).
// 3-stage cp.async: raw X fp32 + pre-split B bf16. A converted smem->smem
// into a double-buffered bf16 hi/lo region each tile.
#define G_BM 128
#define G_BN 256
#define G_BK 32
#define NKT  (FIN / G_BK)   // 16
#define NSTG 3
#define SA 40     // conv A row stride (bf16): conflict-free ldsm (proven R4)
#define SB 264    // B row stride (bf16): conflict-free ldsm.trans (proven R7)
// byte offsets in dynamic smem
#define RAW_OFF(s)  ((s) * 16384)                       // 128*32*4
#define BHI_OFF(s)  (49152 + (s) * 16896)               // 32*264*2
#define BLO_OFF(s)  (99840 + (s) * 16896)
#define ACV_OFF(b)  (150528 + (b) * 20480)              // hi@+0, lo@+10240
#define GEMM_SMEM_BYTES 191488

__global__ __launch_bounds__(256, 1)
void gat_gemm_kernel(const float* __restrict__ X, float* __restrict__ out)
{
    extern __shared__ char smc[];
    const unsigned sbase = (unsigned)__cvta_generic_to_shared(smc);

    const int tid  = threadIdx.x;
    const int lane = tid & 31;
    const int wid  = tid >> 5;
    const int warp_m = wid & 1;   // 64 rows
    const int warp_n = wid >> 1;  // 64 cols

    const float* Ap = X + (size_t)blockIdx.x * G_BM * FIN;

    float c[4][8][4];
    #pragma unroll
    for (int mt = 0; mt < 4; mt++)
        #pragma unroll
        for (int nt = 0; nt < 8; nt++)
            #pragma unroll
            for (int i = 0; i < 4; i++) c[mt][nt][i] = 0.0f;

    // issue cp.async for one k-tile into stage s
    auto issue_stage = [&](int s, int t) {
        #pragma unroll
        for (int l = 0; l < 4; l++) {
            const int ia = tid + l * 256;            // X: 1024 16B chunks
            const int row = ia >> 3, c4 = ia & 7;
            cp_async16(sbase + RAW_OFF(s) + (unsigned)(row * 128 + c4 * 16),
                       Ap + (size_t)row * FIN + t * G_BK + c4 * 4);
            const int br = ia >> 5, c16 = ia & 31;   // B: 1024 16B chunks each
            const int goff = (t * G_BK + br) * FOUT + c16 * 8;
            const unsigned so = (unsigned)(br * SB + c16 * 8) * 2u;
            cp_async16(sbase + BHI_OFF(s) + so, &g_W_hi[goff]);
            cp_async16(sbase + BLO_OFF(s) + so, &g_W_lo[goff]);
        }
    };
    // convert raw X (stage s) -> bf16 hi/lo conv buffer b (own bytes only)
    auto convertA = [&](int b, int s) {
        const float* raw = reinterpret_cast<const float*>(smc + RAW_OFF(s));
        __nv_bfloat16* dst = reinterpret_cast<__nv_bfloat16*>(smc + ACV_OFF(b));
        #pragma unroll
        for (int l = 0; l < 4; l++) {
            const int ia = tid + l * 256;
            const int row = ia >> 3, c4 = ia & 7;
            const float4 v = *reinterpret_cast<const float4*>(raw + row * 32 + c4 * 4);
            const float h0 = __bfloat162float(__float2bfloat16(v.x));
            const float h1 = __bfloat162float(__float2bfloat16(v.y));
            const float h2 = __bfloat162float(__float2bfloat16(v.z));
            const float h3 = __bfloat162float(__float2bfloat16(v.w));
            const int off = row * SA + c4 * 4;
            *reinterpret_cast<uint2*>(dst + off) =
                make_uint2(pack_bf16x2(v.x, v.y), pack_bf16x2(v.z, v.w));
            *reinterpret_cast<uint2*>(dst + 5120 + off) =   // lo at +10240B
                make_uint2(pack_bf16x2(v.x - h0, v.y - h1), pack_bf16x2(v.z - h2, v.w - h3));
        }
    };

    // prologue: fill all 3 stages
    issue_stage(0, 0); CP_COMMIT();
    issue_stage(1, 1); CP_COMMIT();
    issue_stage(2, 2); CP_COMMIT();
    int tin = NSTG;

    #pragma unroll 1
    for (int t = 0; t < NKT; t++) {
        if (t < NKT - 2)       cp_wait<2>();
        else if (t == NKT - 2) cp_wait<1>();
        else                   cp_wait<0>();

        const int s = t % NSTG;
        const int b = t & 1;
        convertA(b, s);
        __syncthreads();               // conv A + all B copies visible

        // ---- mma on conv buf b + B stage s ----
        {
            const unsigned ahb = sbase + ACV_OFF(b);
            const unsigned bhb = sbase + BHI_OFF(s);
            const unsigned blb = sbase + BLO_OFF(s);
            #pragma unroll
            for (int ks = 0; ks < 2; ks++) {
                unsigned ahi[4][4], alo[4][4];
                const int arow = warp_m * 64 + (lane & 15);
                const int acol = ks * 16 + (lane >> 4) * 8;
                #pragma unroll
                for (int mt = 0; mt < 4; mt++) {
                    const unsigned ao = 2u * (unsigned)((arow + mt * 16) * SA + acol);
                    ldsm_x4(ahi[mt], ahb + ao);
                    ldsm_x4(alo[mt], ahb + 10240u + ao);
                }
                const int brow = ks * 16 + (lane & 15);
                #pragma unroll
                for (int half = 0; half < 2; half++) {
                    unsigned bhi[4][2], blo[4][2];
                    #pragma unroll
                    for (int nt = 0; nt < 4; nt++) {
                        const unsigned bo =
                            2u * (unsigned)(brow * SB + warp_n * 64 + half * 32 + nt * 8);
                        ldsm_x2_t(bhi[nt], bhb + bo);
                        ldsm_x2_t(blo[nt], blb + bo);
                    }
                    #pragma unroll
                    for (int mt = 0; mt < 4; mt++)
                        #pragma unroll
                        for (int nt = 0; nt < 4; nt++) {
                            float* cc = c[mt][half * 4 + nt];
                            mma_bf16(cc, ahi[mt], bhi[nt]);
                            mma_bf16(cc, ahi[mt], blo[nt]);
                            mma_bf16(cc, alo[mt], bhi[nt]);
                        }
                }
            }
        }
        __syncthreads();               // all reads of stage s done

        if (tin < NKT) {               // refill stage s with tile t+3
            issue_stage(tin % NSTG, tin); CP_COMMIT(); tin++;
        }
    }

    // epilogue: write h into out[..., 256:512]
    const int row0 = blockIdx.x * G_BM + warp_m * 64 + (lane >> 2);
    const int col0 = warp_n * 64 + (lane & 3) * 2;
    #pragma unroll
    for (int mt = 0; mt < 4; mt++) {
        #pragma unroll
        for (int nt = 0; nt < 8; nt++) {
            float* p0 = out + (size_t)(row0 + mt * 16) * 512 + 256 + col0 + nt * 8;
            float* p1 = out + (size_t)(row0 + mt * 16 + 8) * 512 + 256 + col0 + nt * 8;
            *reinterpret_cast<float2*>(p0) = make_float2(c[mt][nt][0], c[mt][nt][1]);
            *reinterpret_cast<float2*>(p1) = make_float2(c[mt][nt][2], c[mt][nt][3]);
        }
    }
}

// ===================== Phase 2: attention (R4 kernel, 132.6us) =============
#define MB_STRIDE 76
#define SM_HS   0
#define SM_MB   (SM_HS + NNODE * FOUT)            // 19200
#define SM_SV   (SM_MB + 76 * MB_STRIDE)          // 24976
#define SM_TV   (SM_SV + 80)                      // 25056
#define ATTN_SMEM_BYTES ((SM_TV + 80) * 4)        // 100544

__global__ __launch_bounds__(256, 2)
void gat_attn_kernel(const int* __restrict__ A,
                     const float* __restrict__ avec,  // [2*256]
                     float* __restrict__ out)
{
    extern __shared__ float smf[];
    float* hs = smf + SM_HS;
    float* mb = smf + SM_MB;
    float* sv = smf + SM_SV;
    float* tv = smf + SM_TV;

    const int b    = blockIdx.x;
    const int tid  = threadIdx.x;
    const int warp = tid >> 5;
    const int lane = tid & 31;

    float* outb = out + (size_t)b * NNODE * 512;
    const float* hsrc = outb + 256;

    for (int idx = tid; idx < NNODE * (FOUT / 4); idx += 256) {
        const int i  = idx >> 6;
        const int f4 = idx & 63;
        *reinterpret_cast<float4*>(&hs[i * FOUT + f4 * 4]) =
            *reinterpret_cast<const float4*>(hsrc + (size_t)i * 512 + f4 * 4);
    }
    for (int idx = tid; idx < NNODE * NNODE; idx += 256)
        mb[(idx / NNODE) * MB_STRIDE + (idx % NNODE)] = A[idx] ? 0.0f : -1.0e9f;
    if (tid < MB_STRIDE) mb[75 * MB_STRIDE + tid] = 0.0f;
    __syncthreads();

    for (int i = warp; i < NNODE; i += 8) {
        float s0 = 0.0f, s1 = 0.0f;
        #pragma unroll
        for (int r = 0; r < 8; r++) {
            const int f = lane + r * 32;
            const float hv = hs[i * FOUT + f];
            s0 = fmaf(hv, avec[f], s0);
            s1 = fmaf(hv, avec[256 + f], s1);
        }
        #pragma unroll
        for (int o = 16; o; o >>= 1) {
            s0 += __shfl_xor_sync(0xffffffffu, s0, o);
            s1 += __shfl_xor_sync(0xffffffffu, s1, o);
        }
        if (lane == 0) { sv[i] = s0; tv[i] = s1; }
    }
    __syncthreads();

    for (int i = warp; i < NNODE; i += 8) {
        const float si = sv[i];
        float ev[3];
        float m = -3.0e38f;
        #pragma unroll
        for (int r = 0; r < 3; r++) {
            const int j = lane + r * 32;
            float e;
            if (j < NNODE) {
                e = si + tv[j];
                e = (e > 0.0f) ? e : 0.2f * e;
                e += mb[i * MB_STRIDE + j];
            } else {
                e = -3.0e38f;
            }
            ev[r] = e;
            m = fmaxf(m, e);
        }
        #pragma unroll
        for (int o = 16; o; o >>= 1)
            m = fmaxf(m, __shfl_xor_sync(0xffffffffu, m, o));
        float sum = 0.0f;
        #pragma unroll
        for (int r = 0; r < 3; r++) {
            const int j = lane + r * 32;
            const float p = (j < NNODE) ? __expf(ev[r] - m) : 0.0f;
            ev[r] = p;
            sum += p;
        }
        #pragma unroll
        for (int o = 16; o; o >>= 1)
            sum += __shfl_xor_sync(0xffffffffu, sum, o);
        const float inv = 1.0f / sum;
        #pragma unroll
        for (int r = 0; r < 3; r++) {
            const int j = lane + r * 32;
            if (j < NNODE) mb[i * MB_STRIDE + j] = ev[r] * inv;
        }
    }
    __syncthreads();

    const int g  = tid >> 6;
    const int c4 = tid & 63;
    const float4* hs4 = reinterpret_cast<const float4*>(hs);

    float4 acc[19];
    #pragma unroll
    for (int r = 0; r < 19; r++) acc[r] = make_float4(0.f, 0.f, 0.f, 0.f);

    #pragma unroll 1
    for (int j = 0; j < NNODE; j++) {
        const float4 hv = hs4[j * 64 + c4];
        const float* ap = &mb[g * MB_STRIDE + j];
        #pragma unroll
        for (int r = 0; r < 19; r++) {
            const float a = ap[r * 4 * MB_STRIDE];
            acc[r].x = fmaf(a, hv.x, acc[r].x);
            acc[r].y = fmaf(a, hv.y, acc[r].y);
            acc[r].z = fmaf(a, hv.z, acc[r].z);
            acc[r].w = fmaf(a, hv.w, acc[r].w);
        }
    }
    #pragma unroll
    for (int r = 0; r < 19; r++) {
        const int row = g + 4 * r;
        if (row < NNODE)
            *reinterpret_cast<float4*>(outb + (size_t)row * 512 + c4 * 4) = acc[r];
    }
}

// ===========================================================================

extern "C" void kernel_launch(void* const* d_in, const int* in_sizes, int n_in,
                              void* d_out, int out_size)
{
    const float* X = (const float*)d_in[0];
    const int*   A = (const int*)d_in[1];
    const float* W = (const float*)d_in[2];
    const float* a = (const float*)d_in[3];
    float* out = (float*)d_out;

    cudaFuncSetAttribute(gat_gemm_kernel,
                         cudaFuncAttributeMaxDynamicSharedMemorySize, GEMM_SMEM_BYTES);
    cudaFuncSetAttribute(gat_attn_kernel,
                         cudaFuncAttributeMaxDynamicSharedMemorySize, ATTN_SMEM_BYTES);

    w_split_kernel<<<(FIN * FOUT + 255) / 256, 256>>>(W);
    gat_gemm_kernel<<<MROWS / G_BM, 256, GEMM_SMEM_BYTES>>>(X, out);
    gat_attn_kernel<<<BATCH, 256, ATTN_SMEM_BYTES>>>(A, a, out);
}

// round 13
// speedup vs baseline: 1.4631x; 1.4467x over previous
#include <cuda_runtime.h>
#include <cuda_fp16.h>
#include <cuda_bf16.h>
#include <cstdint>
#include <cstring>

// ---------------------------------------------------------------------------
// GAT layer: out = concat( softmax(mask(lrelu(s_i + t_j))) @ h , h )
//   X:[1024,75,512] fp32  A:[75,75] int32  W:[512,256] fp32  a:[2,256,1] fp32
//   out:[1024,75,512] fp32
// Toolchain targets sm_100 (no 'a') -> tcgen05 unavailable; legacy mma.sync
// is ~quarter-rate, so the GEMM is mma-throughput bound: single-pass fp16
// (rel_err ~2e-4 << 1e-3) cuts tensor work 3x vs the bf16 3-term split.
// B loader uses the R8-proven chunk indexing (32 rows x 32 chunks of 16B).
// Phase 0: W -> fp16 scratch ([k][n])
// Phase 1: h = X @ W, mma.sync fp16, cp.async 3-stage pipeline
// Phase 2: attention + aggregation (R4 kernel, measured 132.6us)
// ---------------------------------------------------------------------------

#define BATCH 1024
#define NNODE 75
#define FIN   512
#define FOUT  256
#define MROWS (BATCH * NNODE)   // 76800

// ===================== Phase 0: W fp16 prepass =============================
__device__ __half g_W_h[FIN * FOUT];   // [k][n]

__global__ void w_half_kernel(const float* __restrict__ W) {
    const int idx = blockIdx.x * 256 + threadIdx.x;
    if (idx < FIN * FOUT) g_W_h[idx] = __float2half_rn(W[idx]);
}

// ===================== helpers =============================================
__device__ __forceinline__ unsigned pack_h2(float a, float b) {
    __half2 t = __floats2half2_rn(a, b);
    unsigned u; memcpy(&u, &t, 4); return u;
}
__device__ __forceinline__ void ldsm_x4(unsigned r[4], unsigned addr) {
    asm volatile("ldmatrix.sync.aligned.m8n8.x4.shared.b16 {%0,%1,%2,%3}, [%4];"
                 : "=r"(r[0]), "=r"(r[1]), "=r"(r[2]), "=r"(r[3]) : "r"(addr));
}
__device__ __forceinline__ void ldsm_x2_t(unsigned r[2], unsigned addr) {
    asm volatile("ldmatrix.sync.aligned.m8n8.x2.trans.shared.b16 {%0,%1}, [%2];"
                 : "=r"(r[0]), "=r"(r[1]) : "r"(addr));
}
__device__ __forceinline__ void mma_f16(float d[4], const unsigned a[4], const unsigned b[2]) {
    asm volatile(
        "mma.sync.aligned.m16n8k16.row.col.f32.f16.f16.f32 "
        "{%0,%1,%2,%3},{%4,%5,%6,%7},{%8,%9},{%0,%1,%2,%3};"
        : "+f"(d[0]), "+f"(d[1]), "+f"(d[2]), "+f"(d[3])
        : "r"(a[0]), "r"(a[1]), "r"(a[2]), "r"(a[3]), "r"(b[0]), "r"(b[1]));
}
__device__ __forceinline__ void cp_async16(unsigned dst, const void* src) {
    asm volatile("cp.async.cg.shared.global [%0], [%1], 16;" :: "r"(dst), "l"(src));
}
#define CP_COMMIT() asm volatile("cp.async.commit_group;" ::: "memory")
template<int N> __device__ __forceinline__ void cp_wait() {
    asm volatile("cp.async.wait_group %0;" :: "n"(N) : "memory");
}

// ===================== Phase 1: GEMM =======================================
// M=76800 K=512 N=256. CTA 128x256, BK=32, 256 thr, warp tile 64x64 (2x4).
// 3-stage cp.async: raw X fp32 + fp16 W. A converted smem->smem fp16 into a
// double-buffered region each tile.
#define G_BM 128
#define G_BN 256
#define G_BK 32
#define NKT  (FIN / G_BK)   // 16
#define NSTG 3
#define SA 40     // conv A row stride (fp16): conflict-free ldsm (proven R4)
#define SB 264    // B row stride (fp16): conflict-free ldsm.trans (proven R7)
// byte offsets in dynamic smem
#define RAW_OFF(s)  ((s) * 16384)                 // 128*32*4
#define BH_OFF(s)   (49152 + (s) * 16896)         // 32*264*2
#define ACV_OFF(b)  (99840 + (b) * 10240)         // 128*40*2
#define GEMM_SMEM_BYTES 120320

__global__ __launch_bounds__(256, 1)
void gat_gemm_kernel(const float* __restrict__ X, float* __restrict__ out)
{
    extern __shared__ char smc[];
    const unsigned sbase = (unsigned)__cvta_generic_to_shared(smc);

    const int tid  = threadIdx.x;
    const int lane = tid & 31;
    const int wid  = tid >> 5;
    const int warp_m = wid & 1;   // 64 rows
    const int warp_n = wid >> 1;  // 64 cols

    const float* Ap = X + (size_t)blockIdx.x * G_BM * FIN;

    float c[4][8][4];
    #pragma unroll
    for (int mt = 0; mt < 4; mt++)
        #pragma unroll
        for (int nt = 0; nt < 8; nt++)
            #pragma unroll
            for (int i = 0; i < 4; i++) c[mt][nt][i] = 0.0f;

    // issue cp.async for one k-tile into stage s
    auto issue_stage = [&](int s, int t) {
        #pragma unroll
        for (int l = 0; l < 4; l++) {
            const int ia = tid + l * 256;            // X: 1024 16B chunks
            const int row = ia >> 3, c4 = ia & 7;
            cp_async16(sbase + RAW_OFF(s) + (unsigned)(row * 128 + c4 * 16),
                       Ap + (size_t)row * FIN + t * G_BK + c4 * 4);
            // B: 1024 16B chunks (32 rows x 32 chunks of 8 halves) — R8 indexing
            const int br = ia >> 5, c16 = ia & 31;
            const int goff = (t * G_BK + br) * FOUT + c16 * 8;
            cp_async16(sbase + BH_OFF(s) + (unsigned)(br * SB + c16 * 8) * 2u,
                       &g_W_h[goff]);
        }
    };
    // convert raw X (stage s) -> fp16 conv buffer b
    auto convertA = [&](int b, int s) {
        const float* raw = reinterpret_cast<const float*>(smc + RAW_OFF(s));
        __half* dst = reinterpret_cast<__half*>(smc + ACV_OFF(b));
        #pragma unroll
        for (int l = 0; l < 4; l++) {
            const int ia = tid + l * 256;
            const int row = ia >> 3, c4 = ia & 7;
            const float4 v = *reinterpret_cast<const float4*>(raw + row * 32 + c4 * 4);
            *reinterpret_cast<uint2*>(dst + row * SA + c4 * 4) =
                make_uint2(pack_h2(v.x, v.y), pack_h2(v.z, v.w));
        }
    };

    // prologue: fill all 3 stages
    issue_stage(0, 0); CP_COMMIT();
    issue_stage(1, 1); CP_COMMIT();
    issue_stage(2, 2); CP_COMMIT();
    int tin = NSTG;

    #pragma unroll 1
    for (int t = 0; t < NKT; t++) {
        if (t < NKT - 2)       cp_wait<2>();
        else if (t == NKT - 2) cp_wait<1>();
        else                   cp_wait<0>();

        const int s = t % NSTG;
        const int b = t & 1;
        convertA(b, s);
        __syncthreads();               // conv A + B copies visible

        // ---- mma on conv buf b + B stage s ----
        {
            const unsigned ab = sbase + ACV_OFF(b);
            const unsigned bb = sbase + BH_OFF(s);
            #pragma unroll
            for (int ks = 0; ks < 2; ks++) {
                unsigned af[4][4];
                const int arow = warp_m * 64 + (lane & 15);
                const int acol = ks * 16 + (lane >> 4) * 8;
                #pragma unroll
                for (int mt = 0; mt < 4; mt++)
                    ldsm_x4(af[mt], ab + 2u * (unsigned)((arow + mt * 16) * SA + acol));
                const int brow = ks * 16 + (lane & 15);
                #pragma unroll
                for (int half = 0; half < 2; half++) {
                    unsigned bf[4][2];
                    #pragma unroll
                    for (int nt = 0; nt < 4; nt++)
                        ldsm_x2_t(bf[nt], bb + 2u * (unsigned)(
                            brow * SB + warp_n * 64 + half * 32 + nt * 8));
                    #pragma unroll
                    for (int mt = 0; mt < 4; mt++)
                        #pragma unroll
                        for (int nt = 0; nt < 4; nt++)
                            mma_f16(c[mt][half * 4 + nt], af[mt], bf[nt]);
                }
            }
        }
        __syncthreads();               // all reads of stage s done

        if (tin < NKT) {               // refill stage s with tile t+3
            issue_stage(tin % NSTG, tin); CP_COMMIT(); tin++;
        }
    }

    // epilogue: write h into out[..., 256:512]
    const int row0 = blockIdx.x * G_BM + warp_m * 64 + (lane >> 2);
    const int col0 = warp_n * 64 + (lane & 3) * 2;
    #pragma unroll
    for (int mt = 0; mt < 4; mt++) {
        #pragma unroll
        for (int nt = 0; nt < 8; nt++) {
            float* p0 = out + (size_t)(row0 + mt * 16) * 512 + 256 + col0 + nt * 8;
            float* p1 = out + (size_t)(row0 + mt * 16 + 8) * 512 + 256 + col0 + nt * 8;
            *reinterpret_cast<float2*>(p0) = make_float2(c[mt][nt][0], c[mt][nt][1]);
            *reinterpret_cast<float2*>(p1) = make_float2(c[mt][nt][2], c[mt][nt][3]);
        }
    }
}

// ===================== Phase 2: attention (R4 kernel, 132.6us) =============
#define MB_STRIDE 76
#define SM_HS   0
#define SM_MB   (SM_HS + NNODE * FOUT)            // 19200
#define SM_SV   (SM_MB + 76 * MB_STRIDE)          // 24976
#define SM_TV   (SM_SV + 80)                      // 25056
#define ATTN_SMEM_BYTES ((SM_TV + 80) * 4)        // 100544

__global__ __launch_bounds__(256, 2)
void gat_attn_kernel(const int* __restrict__ A,
                     const float* __restrict__ avec,  // [2*256]
                     float* __restrict__ out)
{
    extern __shared__ float smf[];
    float* hs = smf + SM_HS;
    float* mb = smf + SM_MB;
    float* sv = smf + SM_SV;
    float* tv = smf + SM_TV;

    const int b    = blockIdx.x;
    const int tid  = threadIdx.x;
    const int warp = tid >> 5;
    const int lane = tid & 31;

    float* outb = out + (size_t)b * NNODE * 512;
    const float* hsrc = outb + 256;

    for (int idx = tid; idx < NNODE * (FOUT / 4); idx += 256) {
        const int i  = idx >> 6;
        const int f4 = idx & 63;
        *reinterpret_cast<float4*>(&hs[i * FOUT + f4 * 4]) =
            *reinterpret_cast<const float4*>(hsrc + (size_t)i * 512 + f4 * 4);
    }
    for (int idx = tid; idx < NNODE * NNODE; idx += 256)
        mb[(idx / NNODE) * MB_STRIDE + (idx % NNODE)] = A[idx] ? 0.0f : -1.0e9f;
    if (tid < MB_STRIDE) mb[75 * MB_STRIDE + tid] = 0.0f;
    __syncthreads();

    for (int i = warp; i < NNODE; i += 8) {
        float s0 = 0.0f, s1 = 0.0f;
        #pragma unroll
        for (int r = 0; r < 8; r++) {
            const int f = lane + r * 32;
            const float hv = hs[i * FOUT + f];
            s0 = fmaf(hv, avec[f], s0);
            s1 = fmaf(hv, avec[256 + f], s1);
        }
        #pragma unroll
        for (int o = 16; o; o >>= 1) {
            s0 += __shfl_xor_sync(0xffffffffu, s0, o);
            s1 += __shfl_xor_sync(0xffffffffu, s1, o);
        }
        if (lane == 0) { sv[i] = s0; tv[i] = s1; }
    }
    __syncthreads();

    for (int i = warp; i < NNODE; i += 8) {
        const float si = sv[i];
        float ev[3];
        float m = -3.0e38f;
        #pragma unroll
        for (int r = 0; r < 3; r++) {
            const int j = lane + r * 32;
            float e;
            if (j < NNODE) {
                e = si + tv[j];
                e = (e > 0.0f) ? e : 0.2f * e;     // leaky relu
                e += mb[i * MB_STRIDE + j];
            } else {
                e = -3.0e38f;
            }
            ev[r] = e;
            m = fmaxf(m, e);
        }
        #pragma unroll
        for (int o = 16; o; o >>= 1)
            m = fmaxf(m, __shfl_xor_sync(0xffffffffu, m, o));
        float sum = 0.0f;
        #pragma unroll
        for (int r = 0; r < 3; r++) {
            const int j = lane + r * 32;
            const float p = (j < NNODE) ? __expf(ev[r] - m) : 0.0f;
            ev[r] = p;
            sum += p;
        }
        #pragma unroll
        for (int o = 16; o; o >>= 1)
            sum += __shfl_xor_sync(0xffffffffu, sum, o);
        const float inv = 1.0f / sum;
        #pragma unroll
        for (int r = 0; r < 3; r++) {
            const int j = lane + r * 32;
            if (j < NNODE) mb[i * MB_STRIDE + j] = ev[r] * inv;
        }
    }
    __syncthreads();

    const int g  = tid >> 6;
    const int c4 = tid & 63;
    const float4* hs4 = reinterpret_cast<const float4*>(hs);

    float4 acc[19];
    #pragma unroll
    for (int r = 0; r < 19; r++) acc[r] = make_float4(0.f, 0.f, 0.f, 0.f);

    #pragma unroll 1
    for (int j = 0; j < NNODE; j++) {
        const float4 hv = hs4[j * 64 + c4];
        const float* ap = &mb[g * MB_STRIDE + j];
        #pragma unroll
        for (int r = 0; r < 19; r++) {
            const float a = ap[r * 4 * MB_STRIDE];
            acc[r].x = fmaf(a, hv.x, acc[r].x);
            acc[r].y = fmaf(a, hv.y, acc[r].y);
            acc[r].z = fmaf(a, hv.z, acc[r].z);
            acc[r].w = fmaf(a, hv.w, acc[r].w);
        }
    }
    #pragma unroll
    for (int r = 0; r < 19; r++) {
        const int row = g + 4 * r;
        if (row < NNODE)
            *reinterpret_cast<float4*>(outb + (size_t)row * 512 + c4 * 4) = acc[r];
    }
}

// ===========================================================================

extern "C" void kernel_launch(void* const* d_in, const int* in_sizes, int n_in,
                              void* d_out, int out_size)
{
    const float* X = (const float*)d_in[0];
    const int*   A = (const int*)d_in[1];
    const float* W = (const float*)d_in[2];
    const float* a = (const float*)d_in[3];
    float* out = (float*)d_out;

    cudaFuncSetAttribute(gat_gemm_kernel,
                         cudaFuncAttributeMaxDynamicSharedMemorySize, GEMM_SMEM_BYTES);
    cudaFuncSetAttribute(gat_attn_kernel,
                         cudaFuncAttributeMaxDynamicSharedMemorySize, ATTN_SMEM_BYTES);

    w_half_kernel<<<(FIN * FOUT + 255) / 256, 256>>>(W);
    gat_gemm_kernel<<<MROWS / G_BM, 256, GEMM_SMEM_BYTES>>>(X, out);
    gat_attn_kernel<<<BATCH, 256, ATTN_SMEM_BYTES>>>(A, a, out);
}